// round 8
// baseline (speedup 1.0000x reference)
#include <cuda_runtime.h>
#include <cstdint>
#include <math_constants.h>

#define ENC_DIM 512
#define DEC_DIM 1024
#define HID     128
#define BB      64
#define TT      2048

// ---------------- scratch (no cudaMalloc allowed) ----------------
__device__ float g_q[BB * HID];
__device__ float g_scores[BB * TT];
__device__ float g_ctx_part[16][BB][ENC_DIM];
__device__ int   g_mask_u8;

// ---------------- helpers ----------------
__device__ __forceinline__ uint32_t smem_u32(const void* p) {
    uint32_t a;
    asm("{ .reg .u64 t; cvta.to.shared.u64 t, %1; cvt.u32.u64 %0, t; }" : "=r"(a) : "l"(p));
    return a;
}
__device__ __forceinline__ void cp_async16(uint32_t dst, const void* src) {
    asm volatile("cp.async.cg.shared.global [%0], [%1], 16;" :: "r"(dst), "l"(src));
}
#define CP_COMMIT()  asm volatile("cp.async.commit_group;" ::: "memory")
#define CP_WAIT(n)   asm volatile("cp.async.wait_group %0;" :: "n"(n) : "memory")

// ---------------- kernel 0a/0b: detect mask dtype (parallel) ----------------
__global__ void zero_flag_kernel() { g_mask_u8 = 0; }

__global__ void detect_mask_kernel(const uint4* __restrict__ m) {
    int base = blockIdx.x * 256 + threadIdx.x;     // 64 blocks x 256 threads
    uint4 v = m[base + 0 * 16384 % 8192];          // placeholder avoided below
}

// real detector: 8192 uint4 words over 64x128 threads
__global__ void detect_mask_kernel2(const uint4* __restrict__ m) {
    int i = blockIdx.x * 128 + threadIdx.x;        // 0..8191
    uint4 v = m[i];
    int found = (v.x > 1u) | (v.y > 1u) | (v.z > 1u) | (v.w > 1u);
    // warp-reduce to cut atomics
    found = __any_sync(0xffffffffu, found);
    if ((threadIdx.x & 31) == 0 && found) atomicOr(&g_mask_u8, 1);
}

// ---------------- kernel 1: q projection ----------------
__global__ void q_kernel(const float* __restrict__ dec, const float* __restrict__ Ww) {
    __shared__ float sdec[DEC_DIM];
    int b = blockIdx.x;
    for (int i = threadIdx.x; i < DEC_DIM; i += blockDim.x)
        sdec[i] = dec[b * DEC_DIM + i];
    __syncthreads();
    int h = threadIdx.x;
    const float4* wr = (const float4*)(Ww + (size_t)h * DEC_DIM);
    const float4* dr = (const float4*)sdec;
    float acc = 0.f;
#pragma unroll 8
    for (int i = 0; i < DEC_DIM / 4; i++) {
        float4 w4 = wr[i];
        float4 d4 = dr[i];
        acc += w4.x * d4.x + w4.y * d4.y + w4.z * d4.z + w4.w * d4.w;
    }
    g_q[b * HID + h] = acc;
}

// ---------------- kernel 2: scores via tf32 mma.sync, 2-stage cp.async ----------------
// Block tile 128 tokens x 128 hid, KC=32, 2 smem stages (36KB each) -> 72KB
// dynamic smem => 2 CTAs/SM (16 warps) for latency hiding.
// Loader: warp = 4 x 128B contiguous segments (fully coalesced).
#define KC          32
#define PITCH       36
#define TILE_W      (128 * PITCH)            // 4608 words = 18KB
#define STAGE_W     (2 * TILE_W)             // A + B = 36KB
#define NSTAGE      2
#define NCHUNK      (ENC_DIM / KC)           // 16
#define DYN_BYTES   (NSTAGE * STAGE_W * 4)   // 73728 B

__global__ __launch_bounds__(256, 2) void scores_kernel(
    const float* __restrict__ enc, const float* __restrict__ Vw,
    const float* __restrict__ Vb, const float* __restrict__ ww,
    const float* __restrict__ wb)
{
    extern __shared__ unsigned dsm[];
    __shared__ float sVb[HID], sq[HID], sw[HID];
    __shared__ float srow[128];

    int bidx = blockIdx.x;         // 0..1023
    int b    = bidx >> 4;
    int t0   = (bidx & 15) << 7;

    int tid    = threadIdx.x;
    int lane   = tid & 31;
    int wid    = tid >> 5;
    int warp_m = wid >> 1;         // 0..3
    int warp_n = wid & 1;          // 0..1
    int g      = lane >> 2;        // 0..7
    int tig    = lane & 3;         // 0..3

    if (tid < HID) {
        sVb[tid]  = Vb[tid];
        sq[tid]   = g_q[b * HID + tid];
        sw[tid]   = ww[tid];
        srow[tid] = 0.f;
    }

    const float* Ag = enc + ((size_t)(b * TT + t0)) * ENC_DIM;
    uint32_t dyn_addr = smem_u32(dsm);

    auto load_chunk = [&](int c) {
        uint32_t sbA = dyn_addr + ((c & 1) * STAGE_W) * 4;
        uint32_t sbB = sbA + TILE_W * 4;
        int kc = c * KC;
#pragma unroll
        for (int i = 0; i < 4; i++) {
            int idx = tid + i * 256;          // 0..1023
            int row = idx >> 3;               // 0..127
            int k4  = (idx & 7) << 2;         // 0..28 floats
            cp_async16(sbA + (row * PITCH + k4) * 4,
                       Ag + (size_t)row * ENC_DIM + kc + k4);
        }
#pragma unroll
        for (int i = 0; i < 4; i++) {
            int idx = tid + i * 256;
            int row = idx >> 3;
            int k4  = (idx & 7) << 2;
            cp_async16(sbB + (row * PITCH + k4) * 4,
                       Vw + (size_t)row * ENC_DIM + kc + k4);
        }
        CP_COMMIT();
    };

    float c_[2][8][4];
#pragma unroll
    for (int mt = 0; mt < 2; mt++)
#pragma unroll
        for (int nt = 0; nt < 8; nt++)
#pragma unroll
            for (int r = 0; r < 4; r++) c_[mt][nt][r] = 0.f;

    load_chunk(0);
    load_chunk(1);

    for (int c = 0; c < NCHUNK; c++) {
        if (c + 1 < NCHUNK) CP_WAIT(1); else CP_WAIT(0);
        __syncthreads();           // chunk c resident

        const unsigned* As = dsm + (c & 1) * STAGE_W;
        const unsigned* Bs = As + TILE_W;

#pragma unroll
        for (int ks = 0; ks < KC / 8; ks++) {
            int k0 = ks * 8;
            unsigned a[2][4];
#pragma unroll
            for (int mt = 0; mt < 2; mt++) {
                int r0 = warp_m * 32 + mt * 16 + g;
                a[mt][0] = As[r0 * PITCH + k0 + tig];
                a[mt][1] = As[(r0 + 8) * PITCH + k0 + tig];
                a[mt][2] = As[r0 * PITCH + k0 + tig + 4];
                a[mt][3] = As[(r0 + 8) * PITCH + k0 + tig + 4];
            }
#pragma unroll
            for (int nt = 0; nt < 8; nt++) {
                int n0 = warp_n * 64 + nt * 8 + g;
                unsigned b0 = Bs[n0 * PITCH + k0 + tig];
                unsigned b1 = Bs[n0 * PITCH + k0 + tig + 4];
#pragma unroll
                for (int mt = 0; mt < 2; mt++) {
                    asm volatile(
                        "mma.sync.aligned.m16n8k8.row.col.f32.tf32.tf32.f32 "
                        "{%0,%1,%2,%3}, {%4,%5,%6,%7}, {%8,%9}, {%0,%1,%2,%3};"
                        : "+f"(c_[mt][nt][0]), "+f"(c_[mt][nt][1]),
                          "+f"(c_[mt][nt][2]), "+f"(c_[mt][nt][3])
                        : "r"(a[mt][0]), "r"(a[mt][1]), "r"(a[mt][2]), "r"(a[mt][3]),
                          "r"(b0), "r"(b1));
                }
            }
        }
        __syncthreads();           // stage (c&1) consumed by all warps
        if (c + 2 < NCHUNK) load_chunk(c + 2);
    }

    // epilogue: score[t] = sum_c tanh(k + Vb + q) * w  (+wb at store)
#pragma unroll
    for (int mt = 0; mt < 2; mt++) {
#pragma unroll
        for (int rr = 0; rr < 2; rr++) {
            int row = warp_m * 32 + mt * 16 + rr * 8 + g;
            float partial = 0.f;
#pragma unroll
            for (int nt = 0; nt < 8; nt++) {
                int c0 = warp_n * 64 + nt * 8 + 2 * tig;
                float v0 = c_[mt][nt][2 * rr]     + sVb[c0]     + sq[c0];
                float v1 = c_[mt][nt][2 * rr + 1] + sVb[c0 + 1] + sq[c0 + 1];
                partial += tanhf(v0) * sw[c0] + tanhf(v1) * sw[c0 + 1];
            }
            partial += __shfl_xor_sync(0xffffffffu, partial, 1);
            partial += __shfl_xor_sync(0xffffffffu, partial, 2);
            if (tig == 0) atomicAdd(&srow[row], partial);
        }
    }
    __syncthreads();
    if (tid < 128)
        g_scores[b * TT + t0 + tid] = srow[tid] + wb[0];
}

// ---------------- kernel 3: masked softmax per batch row ----------------
__global__ void softmax_kernel(const unsigned char* __restrict__ mask,
                               float* __restrict__ out_w) {
    int b   = blockIdx.x;
    int tid = threadIdx.x;          // 256 threads
    int lane = tid & 31, wid = tid >> 5;
    bool u8 = (g_mask_u8 != 0);
    __shared__ float redm[8];
    __shared__ float reds[8];
    __shared__ float bc[2];

    float vals[8];
    float mx = -CUDART_INF_F;
#pragma unroll
    for (int i = 0; i < 8; i++) {
        int t = tid + i * 256;
        float s = g_scores[b * TT + t];
        unsigned char m = u8 ? mask[b * TT + t] : mask[4 * (size_t)(b * TT + t)];
        if (m) s = -CUDART_INF_F;
        vals[i] = s;
        mx = fmaxf(mx, s);
    }
#pragma unroll
    for (int off = 16; off; off >>= 1)
        mx = fmaxf(mx, __shfl_xor_sync(0xffffffffu, mx, off));
    if (lane == 0) redm[wid] = mx;
    __syncthreads();
    if (tid == 0) {
        float m = redm[0];
#pragma unroll
        for (int w = 1; w < 8; w++) m = fmaxf(m, redm[w]);
        bc[0] = m;
    }
    __syncthreads();
    mx = bc[0];

    float sum = 0.f;
#pragma unroll
    for (int i = 0; i < 8; i++) {
        vals[i] = __expf(vals[i] - mx);
        sum += vals[i];
    }
#pragma unroll
    for (int off = 16; off; off >>= 1)
        sum += __shfl_xor_sync(0xffffffffu, sum, off);
    if (lane == 0) reds[wid] = sum;
    __syncthreads();
    if (tid == 0) {
        float s = 0.f;
#pragma unroll
        for (int w = 0; w < 8; w++) s += reds[w];
        bc[1] = 1.f / s;
    }
    __syncthreads();
    float inv = bc[1];
#pragma unroll
    for (int i = 0; i < 8; i++)
        out_w[b * TT + tid + i * 256] = vals[i] * inv;
}

// ---------------- kernel 4: context partials (t split 16-way) ----------------
__global__ void ctx_partial_kernel(const float* __restrict__ enc,
                                   const float* __restrict__ weights) {
    int seg = blockIdx.x;   // 0..15
    int b   = blockIdx.y;
    int tid = threadIdx.x;  // 128
    __shared__ float ws[128];
    int tbase = seg * 128;
    ws[tid] = weights[b * TT + tbase + tid];
    __syncthreads();

    float4 acc = make_float4(0.f, 0.f, 0.f, 0.f);
    const float4* ep = (const float4*)(enc + ((size_t)b * TT + tbase) * ENC_DIM) + tid;
#pragma unroll 8
    for (int t = 0; t < 128; t++) {
        float4 v = ep[(size_t)t * (ENC_DIM / 4)];
        float w  = ws[t];
        acc.x += v.x * w; acc.y += v.y * w; acc.z += v.z * w; acc.w += v.w * w;
    }
    ((float4*)g_ctx_part)[((size_t)seg * BB + b) * (ENC_DIM / 4) + tid] = acc;
}

__global__ void ctx_combine_kernel(float* __restrict__ out_ctx) {
    int i = blockIdx.x * blockDim.x + threadIdx.x;
    int b = i >> 9, e = i & 511;
    float s = 0.f;
#pragma unroll
    for (int seg = 0; seg < 16; seg++) s += g_ctx_part[seg][b][e];
    out_ctx[i] = s;
}

// ---------------- launch ----------------
extern "C" void kernel_launch(void* const* d_in, const int* in_sizes, int n_in,
                              void* d_out, int out_size) {
    const float*         enc  = (const float*)d_in[0];
    const float*         dec  = (const float*)d_in[1];
    const unsigned char* mask = (const unsigned char*)d_in[2];
    const float*         Vw   = (const float*)d_in[3];
    const float*         Vb   = (const float*)d_in[4];
    const float*         Ww   = (const float*)d_in[5];
    const float*         ww   = (const float*)d_in[6];
    const float*         wb   = (const float*)d_in[7];

    float* out_ctx = (float*)d_out;                    // [B, ENC_DIM]
    float* out_w   = (float*)d_out + BB * ENC_DIM;     // [B, T]

    static int attr_done = 0;
    if (!attr_done) {
        cudaFuncSetAttribute(scores_kernel,
                             cudaFuncAttributeMaxDynamicSharedMemorySize, DYN_BYTES);
        attr_done = 1;
    }

    zero_flag_kernel<<<1, 1>>>();                            // launch 1
    detect_mask_kernel2<<<64, 128>>>((const uint4*)mask);    // launch 2
    q_kernel<<<BB, HID>>>(dec, Ww);                          // launch 3
    scores_kernel<<<1024, 256, DYN_BYTES>>>(enc, Vw, Vb, ww, wb);  // launch 4 (ncu slot)
    softmax_kernel<<<BB, 256>>>(mask, out_w);
    ctx_partial_kernel<<<dim3(16, BB), 128>>>(enc, out_w);
    ctx_combine_kernel<<<(BB * ENC_DIM) / 256, 256>>>(out_ctx);
}

// round 9
// speedup vs baseline: 1.2853x; 1.2853x over previous
#include <cuda_runtime.h>
#include <cuda_fp16.h>
#include <cstdint>
#include <math_constants.h>

#define ENC_DIM 512
#define DEC_DIM 1024
#define HID     128
#define BB      64
#define TT      2048

// ---------------- scratch (no cudaMalloc allowed) ----------------
__device__ float  g_q[BB * HID];
__device__ float  g_scores[BB * TT];
__device__ float  g_ctx_part[16][BB][ENC_DIM];
__device__ int    g_mask_u8;
__device__ __half g_Vw_h[HID * ENC_DIM];

// ---------------- helpers ----------------
__device__ __forceinline__ uint32_t smem_u32(const void* p) {
    uint32_t a;
    asm("{ .reg .u64 t; cvta.to.shared.u64 t, %1; cvt.u32.u64 %0, t; }" : "=r"(a) : "l"(p));
    return a;
}
__device__ __forceinline__ void cp_async16(uint32_t dst, const void* src) {
    asm volatile("cp.async.cg.shared.global [%0], [%1], 16;" :: "r"(dst), "l"(src));
}
#define CP_COMMIT()  asm volatile("cp.async.commit_group;" ::: "memory")
#define CP_WAIT(n)   asm volatile("cp.async.wait_group %0;" :: "n"(n) : "memory")

// ---------------- kernel 0a/0b: detect mask dtype ----------------
__global__ void zero_flag_kernel() { g_mask_u8 = 0; }

__global__ void detect_mask_kernel2(const uint4* __restrict__ m) {
    int i = blockIdx.x * 128 + threadIdx.x;        // 0..8191
    uint4 v = m[i];
    int found = (v.x > 1u) | (v.y > 1u) | (v.z > 1u) | (v.w > 1u);
    found = __any_sync(0xffffffffu, found);
    if ((threadIdx.x & 31) == 0 && found) atomicOr(&g_mask_u8, 1);
}

// ---------------- kernel 1: q projection + Vw fp16 conversion ----------------
__global__ void q_and_convert_kernel(const float* __restrict__ dec,
                                     const float* __restrict__ Ww,
                                     const float* __restrict__ Vw) {
    int blk = blockIdx.x;
    int tid = threadIdx.x;     // 256
    if (blk < BB) {
        __shared__ float sdec[DEC_DIM];
        for (int i = tid; i < DEC_DIM; i += 256)
            sdec[i] = dec[blk * DEC_DIM + i];
        __syncthreads();
        if (tid < HID) {
            const float4* wr = (const float4*)(Ww + (size_t)tid * DEC_DIM);
            const float4* dr = (const float4*)sdec;
            float acc = 0.f;
#pragma unroll 8
            for (int i = 0; i < DEC_DIM / 4; i++) {
                float4 w4 = wr[i];
                float4 d4 = dr[i];
                acc += w4.x * d4.x + w4.y * d4.y + w4.z * d4.z + w4.w * d4.w;
            }
            g_q[blk * HID + tid] = acc;
        }
    } else {
        int idx = (blk - BB) * 256 + tid;          // 0..16383 float4s
        float4 v = ((const float4*)Vw)[idx];
        __half2 h0 = __floats2half2_rn(v.x, v.y);
        __half2 h1 = __floats2half2_rn(v.z, v.w);
        uint2 u;
        u.x = *(unsigned*)&h0;
        u.y = *(unsigned*)&h1;
        ((uint2*)g_Vw_h)[idx] = u;
    }
}

// ---------------- kernel 2: scores via fp16 mma.sync, pipelined ----------------
// Block tile 128 tokens x 128 hid, KC=32 (16 chunks).
// A (enc fp32): LDG-prefetch 2 chunks ahead -> F2FP -> STS, 2 smem stages.
// B (g_Vw_h fp16): cp.async, 4 smem stages. One __syncthreads per chunk.
// PITCH=20 words/row: fragment LDS banks (20g+tig) mod 32 all distinct.
#define KC        32
#define PITCH     20
#define TILE_W    (128 * PITCH)           // 2560 words = 10KB
#define NCHUNK    (ENC_DIM / KC)          // 16
#define A_OFF_W   0
#define B_OFF_W   (2 * TILE_W)
#define DYN_BYTES ((2 + 4) * TILE_W * 4)  // 61440 B

__global__ __launch_bounds__(256, 2) void scores_kernel(
    const float* __restrict__ enc,
    const float* __restrict__ Vb, const float* __restrict__ ww,
    const float* __restrict__ wb)
{
    extern __shared__ unsigned dsm[];
    __shared__ float sVb[HID], sq[HID], sw[HID];
    __shared__ float srow[128];

    int bidx = blockIdx.x;         // 0..1023
    int b    = bidx >> 4;
    int t0   = (bidx & 15) << 7;

    int tid    = threadIdx.x;
    int lane   = tid & 31;
    int wid    = tid >> 5;
    int warp_m = wid >> 1;         // 0..3
    int warp_n = wid & 1;          // 0..1
    int g      = lane >> 2;        // 0..7
    int tig    = lane & 3;         // 0..3

    if (tid < HID) {
        sVb[tid]  = Vb[tid];
        sq[tid]   = g_q[b * HID + tid];
        sw[tid]   = ww[tid];
        srow[tid] = 0.f;
    }

    const float*  Ag  = enc + ((size_t)(b * TT + t0)) * ENC_DIM;
    const __half* Bg  = g_Vw_h;
    uint32_t dyn_addr = smem_u32(dsm);

    float4 R[4];   // prefetch registers: one A chunk (4 x float4 per thread)

    auto ldgA = [&](int c) {
        int kc = c * KC;
#pragma unroll
        for (int i = 0; i < 4; i++) {
            int idx = tid + i * 256;          // 0..1023
            int row = idx >> 3;               // 0..127
            int u   = idx & 7;                // 16B unit
            R[i] = *(const float4*)(Ag + (size_t)row * ENC_DIM + kc + u * 4);
        }
    };
    auto stsA = [&](int c) {
        unsigned* dst = dsm + A_OFF_W + (c & 1) * TILE_W;
#pragma unroll
        for (int i = 0; i < 4; i++) {
            int idx = tid + i * 256;
            int row = idx >> 3;
            int u   = idx & 7;
            __half2 h0 = __floats2half2_rn(R[i].x, R[i].y);
            __half2 h1 = __floats2half2_rn(R[i].z, R[i].w);
            uint2 v;
            v.x = *(unsigned*)&h0;
            v.y = *(unsigned*)&h1;
            *(uint2*)&dst[row * PITCH + u * 2] = v;
        }
    };
    auto ldB = [&](int c) {
        uint32_t sb = dyn_addr + (B_OFF_W + (c & 3) * TILE_W) * 4;
#pragma unroll
        for (int i = 0; i < 2; i++) {
            int idx = tid + i * 256;          // 0..511
            int row = idx >> 2;               // 0..127
            int u   = idx & 3;                // 16B unit (8 halves)
            cp_async16(sb + (row * PITCH + u * 4) * 4,
                       Bg + (size_t)row * ENC_DIM + c * KC + u * 8);
        }
        CP_COMMIT();
    };

    float c_[2][8][4];
#pragma unroll
    for (int mt = 0; mt < 2; mt++)
#pragma unroll
        for (int nt = 0; nt < 8; nt++)
#pragma unroll
            for (int r = 0; r < 4; r++) c_[mt][nt][r] = 0.f;

    // prologue
    ldgA(0);
    ldB(0); ldB(1); ldB(2);
    stsA(0);
    ldgA(1);
    CP_WAIT(2);
    __syncthreads();

    for (int c = 0; c < NCHUNK; c++) {
        // R holds A(c+1): commit it, then refill R with A(c+2), queue B(c+3)
        if (c + 1 < NCHUNK) stsA(c + 1);
        if (c + 2 < NCHUNK) ldgA(c + 2);
        if (c + 3 < NCHUNK) ldB(c + 3); else CP_COMMIT();

        const unsigned* As = dsm + A_OFF_W + (c & 1) * TILE_W;
        const unsigned* Bs = dsm + B_OFF_W + (c & 3) * TILE_W;

#pragma unroll
        for (int ks = 0; ks < 2; ks++) {
            int k0 = ks * 8;                  // word offset of this k16 step
            unsigned a[2][4];
#pragma unroll
            for (int mt = 0; mt < 2; mt++) {
                int r0 = warp_m * 32 + mt * 16 + g;
                a[mt][0] = As[r0 * PITCH + k0 + tig];
                a[mt][1] = As[(r0 + 8) * PITCH + k0 + tig];
                a[mt][2] = As[r0 * PITCH + k0 + tig + 4];
                a[mt][3] = As[(r0 + 8) * PITCH + k0 + tig + 4];
            }
#pragma unroll
            for (int nt = 0; nt < 8; nt++) {
                int n0 = warp_n * 64 + nt * 8 + g;
                unsigned b0 = Bs[n0 * PITCH + k0 + tig];
                unsigned b1 = Bs[n0 * PITCH + k0 + tig + 4];
#pragma unroll
                for (int mt = 0; mt < 2; mt++) {
                    asm volatile(
                        "mma.sync.aligned.m16n8k16.row.col.f32.f16.f16.f32 "
                        "{%0,%1,%2,%3}, {%4,%5,%6,%7}, {%8,%9}, {%0,%1,%2,%3};"
                        : "+f"(c_[mt][nt][0]), "+f"(c_[mt][nt][1]),
                          "+f"(c_[mt][nt][2]), "+f"(c_[mt][nt][3])
                        : "r"(a[mt][0]), "r"(a[mt][1]), "r"(a[mt][2]), "r"(a[mt][3]),
                          "r"(b0), "r"(b1));
                }
            }
        }
        CP_WAIT(2);
        __syncthreads();
    }

    // epilogue: score[t] = sum_c tanh(k + Vb + q) * w  (+wb at store)
#pragma unroll
    for (int mt = 0; mt < 2; mt++) {
#pragma unroll
        for (int rr = 0; rr < 2; rr++) {
            int row = warp_m * 32 + mt * 16 + rr * 8 + g;
            float partial = 0.f;
#pragma unroll
            for (int nt = 0; nt < 8; nt++) {
                int c0 = warp_n * 64 + nt * 8 + 2 * tig;
                float v0 = c_[mt][nt][2 * rr]     + sVb[c0]     + sq[c0];
                float v1 = c_[mt][nt][2 * rr + 1] + sVb[c0 + 1] + sq[c0 + 1];
                partial += tanhf(v0) * sw[c0] + tanhf(v1) * sw[c0 + 1];
            }
            partial += __shfl_xor_sync(0xffffffffu, partial, 1);
            partial += __shfl_xor_sync(0xffffffffu, partial, 2);
            if (tig == 0) atomicAdd(&srow[row], partial);
        }
    }
    __syncthreads();
    if (tid < 128)
        g_scores[b * TT + t0 + tid] = srow[tid] + wb[0];
}

// ---------------- kernel 3: masked softmax per batch row ----------------
__global__ void softmax_kernel(const unsigned char* __restrict__ mask,
                               float* __restrict__ out_w) {
    int b   = blockIdx.x;
    int tid = threadIdx.x;          // 256 threads
    int lane = tid & 31, wid = tid >> 5;
    bool u8 = (g_mask_u8 != 0);
    __shared__ float redm[8];
    __shared__ float reds[8];
    __shared__ float bc[2];

    float vals[8];
    float mx = -CUDART_INF_F;
#pragma unroll
    for (int i = 0; i < 8; i++) {
        int t = tid + i * 256;
        float s = g_scores[b * TT + t];
        unsigned char m = u8 ? mask[b * TT + t] : mask[4 * (size_t)(b * TT + t)];
        if (m) s = -CUDART_INF_F;
        vals[i] = s;
        mx = fmaxf(mx, s);
    }
#pragma unroll
    for (int off = 16; off; off >>= 1)
        mx = fmaxf(mx, __shfl_xor_sync(0xffffffffu, mx, off));
    if (lane == 0) redm[wid] = mx;
    __syncthreads();
    if (tid == 0) {
        float m = redm[0];
#pragma unroll
        for (int w = 1; w < 8; w++) m = fmaxf(m, redm[w]);
        bc[0] = m;
    }
    __syncthreads();
    mx = bc[0];

    float sum = 0.f;
#pragma unroll
    for (int i = 0; i < 8; i++) {
        vals[i] = __expf(vals[i] - mx);
        sum += vals[i];
    }
#pragma unroll
    for (int off = 16; off; off >>= 1)
        sum += __shfl_xor_sync(0xffffffffu, sum, off);
    if (lane == 0) reds[wid] = sum;
    __syncthreads();
    if (tid == 0) {
        float s = 0.f;
#pragma unroll
        for (int w = 0; w < 8; w++) s += reds[w];
        bc[1] = 1.f / s;
    }
    __syncthreads();
    float inv = bc[1];
#pragma unroll
    for (int i = 0; i < 8; i++)
        out_w[b * TT + tid + i * 256] = vals[i] * inv;
}

// ---------------- kernel 4: context partials (t split 16-way) ----------------
__global__ void ctx_partial_kernel(const float* __restrict__ enc,
                                   const float* __restrict__ weights) {
    int seg = blockIdx.x;   // 0..15
    int b   = blockIdx.y;
    int tid = threadIdx.x;  // 128
    __shared__ float ws[128];
    int tbase = seg * 128;
    ws[tid] = weights[b * TT + tbase + tid];
    __syncthreads();

    float4 acc = make_float4(0.f, 0.f, 0.f, 0.f);
    const float4* ep = (const float4*)(enc + ((size_t)b * TT + tbase) * ENC_DIM) + tid;
#pragma unroll 8
    for (int t = 0; t < 128; t++) {
        float4 v = ep[(size_t)t * (ENC_DIM / 4)];
        float w  = ws[t];
        acc.x += v.x * w; acc.y += v.y * w; acc.z += v.z * w; acc.w += v.w * w;
    }
    ((float4*)g_ctx_part)[((size_t)seg * BB + b) * (ENC_DIM / 4) + tid] = acc;
}

__global__ void ctx_combine_kernel(float* __restrict__ out_ctx) {
    int i = blockIdx.x * blockDim.x + threadIdx.x;
    int b = i >> 9, e = i & 511;
    float s = 0.f;
#pragma unroll
    for (int seg = 0; seg < 16; seg++) s += g_ctx_part[seg][b][e];
    out_ctx[i] = s;
}

// ---------------- launch ----------------
extern "C" void kernel_launch(void* const* d_in, const int* in_sizes, int n_in,
                              void* d_out, int out_size) {
    const float*         enc  = (const float*)d_in[0];
    const float*         dec  = (const float*)d_in[1];
    const unsigned char* mask = (const unsigned char*)d_in[2];
    const float*         Vw   = (const float*)d_in[3];
    const float*         Vb   = (const float*)d_in[4];
    const float*         Ww   = (const float*)d_in[5];
    const float*         ww   = (const float*)d_in[6];
    const float*         wb   = (const float*)d_in[7];

    float* out_ctx = (float*)d_out;                    // [B, ENC_DIM]
    float* out_w   = (float*)d_out + BB * ENC_DIM;     // [B, T]

    static int attr_done = 0;
    if (!attr_done) {
        cudaFuncSetAttribute(scores_kernel,
                             cudaFuncAttributeMaxDynamicSharedMemorySize, DYN_BYTES);
        attr_done = 1;
    }

    zero_flag_kernel<<<1, 1>>>();                                  // launch 1
    detect_mask_kernel2<<<64, 128>>>((const uint4*)mask);          // launch 2
    q_and_convert_kernel<<<BB + 64, 256>>>(dec, Ww, Vw);           // launch 3
    scores_kernel<<<1024, 256, DYN_BYTES>>>(enc, Vb, ww, wb);      // launch 4 (ncu slot)
    softmax_kernel<<<BB, 256>>>(mask, out_w);
    ctx_partial_kernel<<<dim3(16, BB), 128>>>(enc, out_w);
    ctx_combine_kernel<<<(BB * ENC_DIM) / 256, 256>>>(out_ctx);
}